// round 13
// baseline (speedup 1.0000x reference)
#include <cuda_runtime.h>
#include <cuda_fp16.h>
#include <cstdint>

#define NN 50000
#define EE 800000
#define E2T (EE + NN)
#define IN_F 128
#define ED_F 16
#define F1 128
#define HEADS 4
#define HID 32
#define OUTF 32
#define NEG_SLOPE 0.2f

// ---------------- scratch ----------------
__device__ __align__(16) __half g_h1h[(size_t)NN * F1];   // layer1 features (fp16 gather source)
__device__ __align__(16) __half g_h2h[(size_t)NN * OUTF]; // layer2 features (fp16 gather source)
__device__ __align__(16) float4 g_saed1[(size_t)E2T];
__device__ __align__(8)  float2 g_sb[(size_t)E2T];        // (aed2, src bits)
__device__ int      g_count[NN];
__device__ int      g_rowstart[NN];
__device__ int      g_cursor[NN];
__device__ int      g_total;
__device__ float    g_asrc1[NN * HEADS], g_adst1[NN * HEADS];
__device__ float    g_asrc2[NN], g_adst2[NN];
__device__ float    g_wae1[ED_F * HEADS];
__device__ float    g_wae2[ED_F];
__device__ float    g_emean[ED_F];
__device__ int      g_is64;

__device__ __forceinline__ void load_edge(const void* eidx, int e, int is64, int& se, int& de) {
    if (is64) {
        const long long* p = (const long long*)eidx;
        se = (int)p[e];
        de = (int)p[(size_t)EE + e];
    } else {
        const int* p = (const int*)eidx;
        se = p[e];
        de = p[EE + e];
    }
}

__device__ __forceinline__ unsigned long long fma2(unsigned long long a, unsigned long long b,
                                                   unsigned long long c) {
    unsigned long long d;
    asm("fma.rn.f32x2 %0, %1, %2, %3;" : "=l"(d) : "l"(a), "l"(b), "l"(c));
    return d;
}
__device__ __forceinline__ float pairsum(unsigned long long v) {
    float lo, hi;
    asm("mov.b64 {%0, %1}, %2;" : "=f"(lo), "=f"(hi) : "l"(v));
    return lo + hi;
}
__device__ __forceinline__ float4 gather_h4(const __half* p) {
    uint2 u = *reinterpret_cast<const uint2*>(p);
    __half2 a = *reinterpret_cast<__half2*>(&u.x);
    __half2 b = *reinterpret_cast<__half2*>(&u.y);
    float2 fa = __half22float2(a);
    float2 fb = __half22float2(b);
    return make_float4(fa.x, fa.y, fb.x, fb.y);
}

// ---------------- setup ----------------
__global__ void setup(const void* eidx,
                      const float* __restrict__ We1, const float* __restrict__ ae1,
                      const float* __restrict__ We2, const float* __restrict__ ae2) {
    int i = blockIdx.x * blockDim.x + threadIdx.x;
    if (i < NN) g_count[i] = 0;
    if (i < ED_F) g_emean[i] = 0.f;
    if (i == 0) g_total = 0;
    if (blockIdx.x == 0 && threadIdx.x < 32) {
        const int* p = (const int*)eidx;
        int lane = threadIdx.x;
        int allzero = 1;
        #pragma unroll
        for (int k = 0; k < 8; k++)
            if (p[2 * (lane * 8 + k) + 1] != 0) allzero = 0;
        unsigned vote = __ballot_sync(0xffffffffu, allzero);
        if (lane == 0) g_is64 = (vote == 0xffffffffu) ? 1 : 0;
    }
    if (blockIdx.x == 1) {
        int t = threadIdx.x;
        if (t < ED_F * HEADS) {
            int d = t >> 2, h = t & 3;
            float s = 0.f;
            #pragma unroll
            for (int c = 0; c < HID; c++) s += We1[d * F1 + h * HID + c] * ae1[h * HID + c];
            g_wae1[t] = s;
        } else if (t < ED_F * HEADS + ED_F) {
            int d = t - ED_F * HEADS;
            float s = 0.f;
            #pragma unroll
            for (int c = 0; c < OUTF; c++) s += We2[d * OUTF + c] * ae2[c];
            g_wae2[d] = s;
        }
    }
}

// ---------------- CSR count ----------------
__global__ void count_edges(const void* __restrict__ eidx) {
    int base = 4 * (blockIdx.x * blockDim.x + threadIdx.x);
    int is64 = g_is64;
    #pragma unroll
    for (int i = 0; i < 4; i++) {
        int e = base + i;
        if (e < EE) {
            int de;
            if (is64) de = (int)((const long long*)eidx)[(size_t)EE + e];
            else      de = ((const int*)eidx)[EE + e];
            atomicAdd(&g_count[de], 1);
        }
    }
}

// ---------------- parallel segment assignment ----------------
__global__ void assign_rows() {
    __shared__ int sh[256];
    __shared__ int sbase;
    int tid = threadIdx.x;
    int n = blockIdx.x * 256 + tid;
    int deg = (n < NN) ? g_count[n] + 1 : 0;
    sh[tid] = deg;
    __syncthreads();
    #pragma unroll
    for (int o = 1; o < 256; o <<= 1) {
        int v = (tid >= o) ? sh[tid - o] : 0;
        __syncthreads();
        sh[tid] += v;
        __syncthreads();
    }
    int incl = sh[tid];
    if (tid == 255) sbase = atomicAdd(&g_total, incl);
    __syncthreads();
    if (n < NN) {
        int rs = sbase + incl - deg;
        g_rowstart[n] = rs;
        g_cursor[n] = rs + 1;
    }
}

// ---------------- edge dots + CSR scatter + emean ----------------
__global__ void edge_dots_scatter(const void* __restrict__ eidx, const float* __restrict__ ea) {
    __shared__ float4 swae1[ED_F];
    __shared__ float  swae2[ED_F];
    __shared__ float  s16[ED_F];
    if (threadIdx.x < ED_F) {
        swae1[threadIdx.x] = *reinterpret_cast<const float4*>(&g_wae1[threadIdx.x * HEADS]);
        swae2[threadIdx.x] = g_wae2[threadIdx.x];
        s16[threadIdx.x] = 0.f;
    }
    __syncthreads();
    int e = blockIdx.x * blockDim.x + threadIdx.x;
    float4 q[4];
    if (e < EE) {
        const float4* eav = reinterpret_cast<const float4*>(ea + (size_t)e * ED_F);
        #pragma unroll
        for (int i = 0; i < 4; i++) q[i] = eav[i];
        float a0 = 0.f, a1 = 0.f, a2 = 0.f, a3 = 0.f, a4 = 0.f;
        #pragma unroll
        for (int i = 0; i < 4; i++) {
            const float* v = &q[i].x;
            #pragma unroll
            for (int j = 0; j < 4; j++) {
                int d = i * 4 + j;
                float vv = v[j];
                float4 w = swae1[d];
                a0 += vv * w.x;
                a1 += vv * w.y;
                a2 += vv * w.z;
                a3 += vv * w.w;
                a4 += vv * swae2[d];
            }
        }
        int se, de;
        load_edge(eidx, e, g_is64, se, de);
        int pos = atomicAdd(&g_cursor[de], 1);
        g_saed1[pos] = make_float4(a0, a1, a2, a3);
        g_sb[pos] = make_float2(a4, __int_as_float(se));
    } else {
        #pragma unroll
        for (int i = 0; i < 4; i++) q[i] = make_float4(0.f, 0.f, 0.f, 0.f);
    }
    #pragma unroll
    for (int o = 16; o; o >>= 1) {
        #pragma unroll
        for (int i = 0; i < 4; i++) {
            q[i].x += __shfl_xor_sync(0xffffffffu, q[i].x, o);
            q[i].y += __shfl_xor_sync(0xffffffffu, q[i].y, o);
            q[i].z += __shfl_xor_sync(0xffffffffu, q[i].z, o);
            q[i].w += __shfl_xor_sync(0xffffffffu, q[i].w, o);
        }
    }
    if ((threadIdx.x & 31) == 0) {
        #pragma unroll
        for (int i = 0; i < 4; i++) {
            atomicAdd(&s16[i * 4 + 0], q[i].x);
            atomicAdd(&s16[i * 4 + 1], q[i].y);
            atomicAdd(&s16[i * 4 + 2], q[i].z);
            atomicAdd(&s16[i * 4 + 3], q[i].w);
        }
    }
    __syncthreads();
    if (threadIdx.x < ED_F) atomicAdd(&g_emean[threadIdx.x], s16[threadIdx.x]);
}

// ---------------- self-loop fill ----------------
__global__ void selfloop_fill() {
    __shared__ float sl1s[HEADS];
    __shared__ float sl2s;
    int t = threadIdx.x;
    const float inv_e = 1.f / (float)EE;
    if (t < HEADS) {
        float s = 0.f;
        #pragma unroll
        for (int d = 0; d < ED_F; d++) s += g_emean[d] * inv_e * g_wae1[d * HEADS + t];
        sl1s[t] = s;
    } else if (t == HEADS) {
        float s = 0.f;
        #pragma unroll
        for (int d = 0; d < ED_F; d++) s += g_emean[d] * inv_e * g_wae2[d];
        sl2s = s;
    }
    __syncthreads();
    int n = blockIdx.x * blockDim.x + t;
    if (n >= NN) return;
    int j = g_rowstart[n];
    g_saed1[j] = make_float4(sl1s[0], sl1s[1], sl1s[2], sl1s[3]);
    g_sb[j] = make_float2(sl2s, __int_as_float(n));
}

// ---------------- GEMM1 (FFMA2): h1(fp16) = x @ W1, fused coef1 ----------------
__global__ void gemm1(const float* __restrict__ A, const float* __restrict__ B,
                      const float* __restrict__ as1, const float* __restrict__ ad1) {
    __shared__ float As[64][IN_F + 4];
    __shared__ float Bst[32][IN_F + 4];
    int row0 = blockIdx.x * 64;
    int tx = threadIdx.x & 31;
    int ty = threadIdx.x >> 5;
    {
        const float4* A4 = reinterpret_cast<const float4*>(A);
        #pragma unroll
        for (int i = 0; i < 8; i++) {
            int idx = threadIdx.x + i * 256;
            int r = idx >> 5, c4 = idx & 31;
            int gr = row0 + r;
            float4 v = (gr < NN) ? A4[(size_t)gr * 32 + c4] : make_float4(0.f, 0.f, 0.f, 0.f);
            *reinterpret_cast<float4*>(&As[r][c4 * 4]) = v;
        }
    }
    for (int cb = 0; cb < HEADS; cb++) {
        __syncthreads();
        #pragma unroll
        for (int i = 0; i < 16; i++) {
            int idx = threadIdx.x + i * 256;
            int r = idx >> 5, c = idx & 31;
            Bst[c][r] = B[(size_t)r * F1 + cb * 32 + c];
        }
        __syncthreads();
        unsigned long long acc2[8];
        #pragma unroll
        for (int r = 0; r < 8; r++) acc2[r] = 0ull;
        #pragma unroll 4
        for (int k2 = 0; k2 < IN_F / 2; k2++) {
            unsigned long long bv = *reinterpret_cast<const unsigned long long*>(&Bst[tx][k2 * 2]);
            #pragma unroll
            for (int r = 0; r < 8; r++) {
                unsigned long long av =
                    *reinterpret_cast<const unsigned long long*>(&As[ty * 8 + r][k2 * 2]);
                acc2[r] = fma2(av, bv, acc2[r]);
            }
        }
        float asv = as1[cb * HID + tx];
        float adv = ad1[cb * HID + tx];
        #pragma unroll
        for (int r = 0; r < 8; r++) {
            float acc = pairsum(acc2[r]);
            int gr = row0 + ty * 8 + r;
            if (gr < NN) g_h1h[(size_t)gr * F1 + cb * 32 + tx] = __float2half_rn(acc);
            float sv = acc * asv;
            float dv = acc * adv;
            #pragma unroll
            for (int o = 16; o; o >>= 1) {
                sv += __shfl_xor_sync(0xffffffffu, sv, o);
                dv += __shfl_xor_sync(0xffffffffu, dv, o);
            }
            if (tx == 0 && gr < NN) {
                g_asrc1[gr * HEADS + cb] = sv;
                g_adst1[gr * HEADS + cb] = dv;
            }
        }
    }
}

// ---------------- FUSED: aggregate layer1 -> smem -> GEMM2 (+coef2), h2 in fp16 ----------------
__global__ void agg1_gemm2(const float* __restrict__ b1, const float* __restrict__ B,
                           const float* __restrict__ as2, const float* __restrict__ ad2) {
    __shared__ float As[64][F1 + 4];   // aggregated+relu rows (gemm A tile)
    __shared__ float Bst[32][F1 + 4];
    int row0 = blockIdx.x * 64;
    int tx = threadIdx.x & 31;
    int wid = threadIdx.x >> 5;   // 8 warps
    // load B panel (128 x 32) transposed
    #pragma unroll
    for (int i = 0; i < 16; i++) {
        int idx = threadIdx.x + i * 256;
        int r = idx >> 5, c = idx & 31;
        Bst[c][r] = B[(size_t)r * OUTF + c];
    }
    // ---- aggregate phase: 8 warps x 8 rounds = 64 nodes ----
    int lane = tx;
    int h4 = lane & 3;
    int hh = lane >> 3;
    float4 bv = *reinterpret_cast<const float4*>(&b1[lane * 4]);
    for (int it = 0; it < 8; it++) {
        int n = row0 + it * 8 + wid;
        float4 o = make_float4(0.f, 0.f, 0.f, 0.f);
        if (n < NN) {
            int beg = g_rowstart[n];
            int end = beg + g_count[n] + 1;
            float adst = (lane < 16) ? g_adst1[n * HEADS + h4] : 0.f;
            float denp = 0.f;
            float4 acc = make_float4(0.f, 0.f, 0.f, 0.f);
            int j = beg;
            for (; j + 4 <= end; j += 4) {
                int sK = (lane < 4) ? __float_as_int(g_sb[j + lane].y) : 0;
                int s0 = __shfl_sync(0xffffffffu, sK, 0);
                int s1 = __shfl_sync(0xffffffffu, sK, 1);
                int s2 = __shfl_sync(0xffffffffu, sK, 2);
                int s3 = __shfl_sync(0xffffffffu, sK, 3);
                float ex = 0.f;
                if (lane < 16) {
                    int k = lane >> 2;
                    int sk = (k == 0) ? s0 : (k == 1) ? s1 : (k == 2) ? s2 : s3;
                    float aed = ((const float*)&g_saed1[j + k])[h4];
                    float lg = g_asrc1[sk * HEADS + h4] + adst + aed;
                    lg = (lg > 0.f) ? lg : NEG_SLOPE * lg;
                    ex = __expf(lg);
                    denp += ex;
                }
                float e0 = __shfl_sync(0xffffffffu, ex, hh);
                float e1 = __shfl_sync(0xffffffffu, ex, 4 + hh);
                float e2 = __shfl_sync(0xffffffffu, ex, 8 + hh);
                float e3 = __shfl_sync(0xffffffffu, ex, 12 + hh);
                float4 v0 = gather_h4(&g_h1h[(size_t)s0 * F1 + lane * 4]);
                float4 v1 = gather_h4(&g_h1h[(size_t)s1 * F1 + lane * 4]);
                float4 v2 = gather_h4(&g_h1h[(size_t)s2 * F1 + lane * 4]);
                float4 v3 = gather_h4(&g_h1h[(size_t)s3 * F1 + lane * 4]);
                acc.x += e0 * v0.x + e1 * v1.x + e2 * v2.x + e3 * v3.x;
                acc.y += e0 * v0.y + e1 * v1.y + e2 * v2.y + e3 * v3.y;
                acc.z += e0 * v0.z + e1 * v1.z + e2 * v2.z + e3 * v3.z;
                acc.w += e0 * v0.w + e1 * v1.w + e2 * v2.w + e3 * v3.w;
            }
            for (; j < end; j++) {
                float2 sb = g_sb[j];
                int se = __float_as_int(sb.y);
                float ex = 0.f;
                if (lane < 4) {
                    float aed = ((const float*)&g_saed1[j])[lane];
                    float lg = g_asrc1[se * HEADS + lane] + adst + aed;
                    lg = (lg > 0.f) ? lg : NEG_SLOPE * lg;
                    ex = __expf(lg);
                    denp += ex;
                }
                float eb = __shfl_sync(0xffffffffu, ex, hh);
                float4 v = gather_h4(&g_h1h[(size_t)se * F1 + lane * 4]);
                acc.x += eb * v.x;
                acc.y += eb * v.y;
                acc.z += eb * v.z;
                acc.w += eb * v.w;
            }
            float den = __shfl_sync(0xffffffffu, denp, hh)
                      + __shfl_sync(0xffffffffu, denp, 4 + hh)
                      + __shfl_sync(0xffffffffu, denp, 8 + hh)
                      + __shfl_sync(0xffffffffu, denp, 12 + hh);
            float inv = 1.f / (den + 1e-16f);
            o.x = fmaxf(acc.x * inv + bv.x, 0.f);
            o.y = fmaxf(acc.y * inv + bv.y, 0.f);
            o.z = fmaxf(acc.z * inv + bv.z, 0.f);
            o.w = fmaxf(acc.w * inv + bv.w, 0.f);
        }
        *reinterpret_cast<float4*>(&As[it * 8 + wid][lane * 4]) = o;
    }
    __syncthreads();
    // ---- gemm phase: h2 = As @ W2, fused coef2, h2 stored fp16 ----
    int ty = wid;
    unsigned long long acc2[8];
    #pragma unroll
    for (int r = 0; r < 8; r++) acc2[r] = 0ull;
    #pragma unroll 4
    for (int k2 = 0; k2 < F1 / 2; k2++) {
        unsigned long long bvv = *reinterpret_cast<const unsigned long long*>(&Bst[tx][k2 * 2]);
        #pragma unroll
        for (int r = 0; r < 8; r++) {
            unsigned long long av =
                *reinterpret_cast<const unsigned long long*>(&As[ty * 8 + r][k2 * 2]);
            acc2[r] = fma2(av, bvv, acc2[r]);
        }
    }
    float asv = as2[tx];
    float adv = ad2[tx];
    #pragma unroll
    for (int r = 0; r < 8; r++) {
        float acc = pairsum(acc2[r]);
        int gr = row0 + ty * 8 + r;
        if (gr < NN) g_h2h[(size_t)gr * OUTF + tx] = __float2half_rn(acc);
        float sv = acc * asv;
        float dv = acc * adv;
        #pragma unroll
        for (int o = 16; o; o >>= 1) {
            sv += __shfl_xor_sync(0xffffffffu, sv, o);
            dv += __shfl_xor_sync(0xffffffffu, dv, o);
        }
        if (tx == 0 && gr < NN) {
            g_asrc2[gr] = sv;
            g_adst2[gr] = dv;
        }
    }
}

// ---------------- aggregate layer 2 (fp16 gather) ----------------
__global__ void aggregate2(float* __restrict__ out, const float* __restrict__ b2) {
    int n = (blockIdx.x * blockDim.x + threadIdx.x) >> 5;
    if (n >= NN) return;
    int lane = threadIdx.x & 31;
    int beg = g_rowstart[n];
    int end = beg + g_count[n] + 1;
    float adst = g_adst2[n];
    float denp = 0.f, acc = 0.f;
    int j = beg;
    for (; j + 4 <= end; j += 4) {
        int sK = 0;
        float ex = 0.f;
        if (lane < 4) {
            float2 sbv = g_sb[j + lane];
            sK = __float_as_int(sbv.y);
            float lg = g_asrc2[sK] + adst + sbv.x;
            lg = (lg > 0.f) ? lg : NEG_SLOPE * lg;
            ex = __expf(lg);
            denp += ex;
        }
        int s0 = __shfl_sync(0xffffffffu, sK, 0);
        int s1 = __shfl_sync(0xffffffffu, sK, 1);
        int s2 = __shfl_sync(0xffffffffu, sK, 2);
        int s3 = __shfl_sync(0xffffffffu, sK, 3);
        float e0 = __shfl_sync(0xffffffffu, ex, 0);
        float e1 = __shfl_sync(0xffffffffu, ex, 1);
        float e2 = __shfl_sync(0xffffffffu, ex, 2);
        float e3 = __shfl_sync(0xffffffffu, ex, 3);
        acc += e0 * __half2float(g_h2h[(size_t)s0 * OUTF + lane])
             + e1 * __half2float(g_h2h[(size_t)s1 * OUTF + lane])
             + e2 * __half2float(g_h2h[(size_t)s2 * OUTF + lane])
             + e3 * __half2float(g_h2h[(size_t)s3 * OUTF + lane]);
    }
    for (; j < end; j++) {
        float2 sb = g_sb[j];
        int se = __float_as_int(sb.y);
        float ex = 0.f;
        if (lane == 0) {
            float lg = g_asrc2[se] + adst + sb.x;
            lg = (lg > 0.f) ? lg : NEG_SLOPE * lg;
            ex = __expf(lg);
            denp += ex;
        }
        float eb = __shfl_sync(0xffffffffu, ex, 0);
        acc += eb * __half2float(g_h2h[(size_t)se * OUTF + lane]);
    }
    float den = __shfl_sync(0xffffffffu, denp, 0)
              + __shfl_sync(0xffffffffu, denp, 1)
              + __shfl_sync(0xffffffffu, denp, 2)
              + __shfl_sync(0xffffffffu, denp, 3);
    out[(size_t)n * OUTF + lane] = acc / (den + 1e-16f) + b2[lane];
}

// ---------------- launch ----------------
extern "C" void kernel_launch(void* const* d_in, const int* in_sizes, int n_in,
                              void* d_out, int out_size) {
    int used[64];
    for (int i = 0; i < n_in && i < 64; i++) used[i] = 0;
    auto take = [&](int want) -> const void* {
        for (int i = 0; i < n_in && i < 64; i++)
            if (!used[i] && in_sizes[i] == want) { used[i] = 1; return d_in[i]; }
        return nullptr;
    };
    const float* x   = (const float*)take(NN * IN_F);
    const void*  eix = take(2 * EE);
    const float* ea  = (const float*)take(EE * ED_F);
    const float* W1  = (const float*)take(IN_F * F1);
    const float* We1 = (const float*)take(ED_F * F1);
    const float* W2  = (const float*)take(F1 * OUTF);
    const float* We2 = (const float*)take(ED_F * OUTF);
    const float* g128[4] = {nullptr, nullptr, nullptr, nullptr};
    const float* g32[4]  = {nullptr, nullptr, nullptr, nullptr};
    int n128 = 0, n32 = 0;
    for (int i = 0; i < n_in && i < 64; i++) {
        if (used[i]) continue;
        if (in_sizes[i] == 128 && n128 < 4) g128[n128++] = (const float*)d_in[i];
        else if (in_sizes[i] == 32 && n32 < 4) g32[n32++] = (const float*)d_in[i];
    }
    const float* as1 = g128[0], *ad1 = g128[1], *ae1 = g128[2], *b1 = g128[3];
    const float* as2 = g32[0],  *ad2 = g32[1],  *ae2 = g32[2],  *b2 = g32[3];
    if (!x || !eix || !ea || !W1 || !We1 || !W2 || !We2 || n128 < 4 || n32 < 4) {
        x   = (const float*)d_in[0];  eix = d_in[1];               ea  = (const float*)d_in[2];
        W1  = (const float*)d_in[3];  We1 = (const float*)d_in[4];
        as1 = (const float*)d_in[5];  ad1 = (const float*)d_in[6]; ae1 = (const float*)d_in[7];
        b1  = (const float*)d_in[8];  W2  = (const float*)d_in[9]; We2 = (const float*)d_in[10];
        as2 = (const float*)d_in[11]; ad2 = (const float*)d_in[12]; ae2 = (const float*)d_in[13];
        b2  = (const float*)d_in[14];
    }
    float* out = (float*)d_out;

    const int TB = 256;

    setup<<<(NN + TB - 1) / TB, TB>>>(eix, We1, ae1, We2, ae2);
    count_edges<<<(EE + TB * 4 - 1) / (TB * 4), TB>>>(eix);
    assign_rows<<<(NN + TB - 1) / TB, TB>>>();
    edge_dots_scatter<<<(EE + TB - 1) / TB, TB>>>(eix, ea);
    selfloop_fill<<<(NN + TB - 1) / TB, TB>>>();

    gemm1<<<(NN + 63) / 64, TB>>>(x, W1, as1, ad1);
    agg1_gemm2<<<(NN + 63) / 64, TB>>>(b1, W2, as2, ad2);
    aggregate2<<<(int)(((size_t)NN * 32 + TB - 1) / TB), TB>>>(out, b2);
}

// round 14
// speedup vs baseline: 1.1583x; 1.1583x over previous
#include <cuda_runtime.h>
#include <cuda_fp16.h>
#include <cstdint>

#define NN 50000
#define EE 800000
#define E2T (EE + NN)
#define IN_F 128
#define ED_F 16
#define F1 128
#define HEADS 4
#define HID 32
#define OUTF 32
#define NEG_SLOPE 0.2f

// ---------------- scratch ----------------
__device__ __align__(16) __half g_h1h[(size_t)NN * F1];   // layer1 features (fp16 gather source)
__device__ __align__(16) float g_hr[(size_t)NN * F1];     // layer1 aggregated+relu (fp32)
__device__ __align__(16) __half g_h2h[(size_t)NN * OUTF]; // layer2 features (fp16 gather source)
__device__ __align__(16) float4 g_saed1[(size_t)E2T];
__device__ __align__(8)  float2 g_sb[(size_t)E2T];        // (aed2, src bits)
__device__ int      g_count[NN];
__device__ int      g_rowstart[NN];
__device__ int      g_cursor[NN];
__device__ int      g_total;
__device__ float    g_asrc1[NN * HEADS], g_adst1[NN * HEADS];
__device__ float    g_asrc2[NN], g_adst2[NN];
__device__ float    g_wae1[ED_F * HEADS];
__device__ float    g_wae2[ED_F];
__device__ float    g_emean[ED_F];
__device__ int      g_is64;

__device__ __forceinline__ void load_edge(const void* eidx, int e, int is64, int& se, int& de) {
    if (is64) {
        const long long* p = (const long long*)eidx;
        se = (int)p[e];
        de = (int)p[(size_t)EE + e];
    } else {
        const int* p = (const int*)eidx;
        se = p[e];
        de = p[EE + e];
    }
}

__device__ __forceinline__ unsigned long long fma2(unsigned long long a, unsigned long long b,
                                                   unsigned long long c) {
    unsigned long long d;
    asm("fma.rn.f32x2 %0, %1, %2, %3;" : "=l"(d) : "l"(a), "l"(b), "l"(c));
    return d;
}
__device__ __forceinline__ float pairsum(unsigned long long v) {
    float lo, hi;
    asm("mov.b64 {%0, %1}, %2;" : "=f"(lo), "=f"(hi) : "l"(v));
    return lo + hi;
}
__device__ __forceinline__ float4 gather_h4(const __half* p) {
    uint2 u = *reinterpret_cast<const uint2*>(p);
    __half2 a = *reinterpret_cast<__half2*>(&u.x);
    __half2 b = *reinterpret_cast<__half2*>(&u.y);
    float2 fa = __half22float2(a);
    float2 fb = __half22float2(b);
    return make_float4(fa.x, fa.y, fb.x, fb.y);
}

// ---------------- setup ----------------
__global__ void setup(const void* eidx,
                      const float* __restrict__ We1, const float* __restrict__ ae1,
                      const float* __restrict__ We2, const float* __restrict__ ae2) {
    int i = blockIdx.x * blockDim.x + threadIdx.x;
    if (i < NN) g_count[i] = 0;
    if (i < ED_F) g_emean[i] = 0.f;
    if (i == 0) g_total = 0;
    if (blockIdx.x == 0 && threadIdx.x < 32) {
        const int* p = (const int*)eidx;
        int lane = threadIdx.x;
        int allzero = 1;
        #pragma unroll
        for (int k = 0; k < 8; k++)
            if (p[2 * (lane * 8 + k) + 1] != 0) allzero = 0;
        unsigned vote = __ballot_sync(0xffffffffu, allzero);
        if (lane == 0) g_is64 = (vote == 0xffffffffu) ? 1 : 0;
    }
    if (blockIdx.x == 1) {
        int t = threadIdx.x;
        if (t < ED_F * HEADS) {
            int d = t >> 2, h = t & 3;
            float s = 0.f;
            #pragma unroll
            for (int c = 0; c < HID; c++) s += We1[d * F1 + h * HID + c] * ae1[h * HID + c];
            g_wae1[t] = s;
        } else if (t < ED_F * HEADS + ED_F) {
            int d = t - ED_F * HEADS;
            float s = 0.f;
            #pragma unroll
            for (int c = 0; c < OUTF; c++) s += We2[d * OUTF + c] * ae2[c];
            g_wae2[d] = s;
        }
    }
}

// ---------------- CSR count ----------------
__global__ void count_edges(const void* __restrict__ eidx) {
    int base = 4 * (blockIdx.x * blockDim.x + threadIdx.x);
    int is64 = g_is64;
    #pragma unroll
    for (int i = 0; i < 4; i++) {
        int e = base + i;
        if (e < EE) {
            int de;
            if (is64) de = (int)((const long long*)eidx)[(size_t)EE + e];
            else      de = ((const int*)eidx)[EE + e];
            atomicAdd(&g_count[de], 1);
        }
    }
}

// ---------------- parallel segment assignment ----------------
__global__ void assign_rows() {
    __shared__ int sh[256];
    __shared__ int sbase;
    int tid = threadIdx.x;
    int n = blockIdx.x * 256 + tid;
    int deg = (n < NN) ? g_count[n] + 1 : 0;
    sh[tid] = deg;
    __syncthreads();
    #pragma unroll
    for (int o = 1; o < 256; o <<= 1) {
        int v = (tid >= o) ? sh[tid - o] : 0;
        __syncthreads();
        sh[tid] += v;
        __syncthreads();
    }
    int incl = sh[tid];
    if (tid == 255) sbase = atomicAdd(&g_total, incl);
    __syncthreads();
    if (n < NN) {
        int rs = sbase + incl - deg;
        g_rowstart[n] = rs;
        g_cursor[n] = rs + 1;
    }
}

// ---------------- edge dots + CSR scatter + emean ----------------
__global__ void edge_dots_scatter(const void* __restrict__ eidx, const float* __restrict__ ea) {
    __shared__ float4 swae1[ED_F];
    __shared__ float  swae2[ED_F];
    __shared__ float  s16[ED_F];
    if (threadIdx.x < ED_F) {
        swae1[threadIdx.x] = *reinterpret_cast<const float4*>(&g_wae1[threadIdx.x * HEADS]);
        swae2[threadIdx.x] = g_wae2[threadIdx.x];
        s16[threadIdx.x] = 0.f;
    }
    __syncthreads();
    int e = blockIdx.x * blockDim.x + threadIdx.x;
    float4 q[4];
    if (e < EE) {
        const float4* eav = reinterpret_cast<const float4*>(ea + (size_t)e * ED_F);
        #pragma unroll
        for (int i = 0; i < 4; i++) q[i] = eav[i];
        float a0 = 0.f, a1 = 0.f, a2 = 0.f, a3 = 0.f, a4 = 0.f;
        #pragma unroll
        for (int i = 0; i < 4; i++) {
            const float* v = &q[i].x;
            #pragma unroll
            for (int j = 0; j < 4; j++) {
                int d = i * 4 + j;
                float vv = v[j];
                float4 w = swae1[d];
                a0 += vv * w.x;
                a1 += vv * w.y;
                a2 += vv * w.z;
                a3 += vv * w.w;
                a4 += vv * swae2[d];
            }
        }
        int se, de;
        load_edge(eidx, e, g_is64, se, de);
        int pos = atomicAdd(&g_cursor[de], 1);
        g_saed1[pos] = make_float4(a0, a1, a2, a3);
        g_sb[pos] = make_float2(a4, __int_as_float(se));
    } else {
        #pragma unroll
        for (int i = 0; i < 4; i++) q[i] = make_float4(0.f, 0.f, 0.f, 0.f);
    }
    #pragma unroll
    for (int o = 16; o; o >>= 1) {
        #pragma unroll
        for (int i = 0; i < 4; i++) {
            q[i].x += __shfl_xor_sync(0xffffffffu, q[i].x, o);
            q[i].y += __shfl_xor_sync(0xffffffffu, q[i].y, o);
            q[i].z += __shfl_xor_sync(0xffffffffu, q[i].z, o);
            q[i].w += __shfl_xor_sync(0xffffffffu, q[i].w, o);
        }
    }
    if ((threadIdx.x & 31) == 0) {
        #pragma unroll
        for (int i = 0; i < 4; i++) {
            atomicAdd(&s16[i * 4 + 0], q[i].x);
            atomicAdd(&s16[i * 4 + 1], q[i].y);
            atomicAdd(&s16[i * 4 + 2], q[i].z);
            atomicAdd(&s16[i * 4 + 3], q[i].w);
        }
    }
    __syncthreads();
    if (threadIdx.x < ED_F) atomicAdd(&g_emean[threadIdx.x], s16[threadIdx.x]);
}

// ---------------- self-loop fill ----------------
__global__ void selfloop_fill() {
    __shared__ float sl1s[HEADS];
    __shared__ float sl2s;
    int t = threadIdx.x;
    const float inv_e = 1.f / (float)EE;
    if (t < HEADS) {
        float s = 0.f;
        #pragma unroll
        for (int d = 0; d < ED_F; d++) s += g_emean[d] * inv_e * g_wae1[d * HEADS + t];
        sl1s[t] = s;
    } else if (t == HEADS) {
        float s = 0.f;
        #pragma unroll
        for (int d = 0; d < ED_F; d++) s += g_emean[d] * inv_e * g_wae2[d];
        sl2s = s;
    }
    __syncthreads();
    int n = blockIdx.x * blockDim.x + t;
    if (n >= NN) return;
    int j = g_rowstart[n];
    g_saed1[j] = make_float4(sl1s[0], sl1s[1], sl1s[2], sl1s[3]);
    g_sb[j] = make_float2(sl2s, __int_as_float(n));
}

// ---------------- GEMM1 (FFMA2): h1(fp16) = x @ W1, fused coef1 ----------------
__global__ void gemm1(const float* __restrict__ A, const float* __restrict__ B,
                      const float* __restrict__ as1, const float* __restrict__ ad1) {
    __shared__ float As[64][IN_F + 4];
    __shared__ float Bst[32][IN_F + 4];
    int row0 = blockIdx.x * 64;
    int tx = threadIdx.x & 31;
    int ty = threadIdx.x >> 5;
    {
        const float4* A4 = reinterpret_cast<const float4*>(A);
        #pragma unroll
        for (int i = 0; i < 8; i++) {
            int idx = threadIdx.x + i * 256;
            int r = idx >> 5, c4 = idx & 31;
            int gr = row0 + r;
            float4 v = (gr < NN) ? A4[(size_t)gr * 32 + c4] : make_float4(0.f, 0.f, 0.f, 0.f);
            *reinterpret_cast<float4*>(&As[r][c4 * 4]) = v;
        }
    }
    for (int cb = 0; cb < HEADS; cb++) {
        __syncthreads();
        #pragma unroll
        for (int i = 0; i < 16; i++) {
            int idx = threadIdx.x + i * 256;
            int r = idx >> 5, c = idx & 31;
            Bst[c][r] = B[(size_t)r * F1 + cb * 32 + c];
        }
        __syncthreads();
        unsigned long long acc2[8];
        #pragma unroll
        for (int r = 0; r < 8; r++) acc2[r] = 0ull;
        #pragma unroll 4
        for (int k2 = 0; k2 < IN_F / 2; k2++) {
            unsigned long long bv = *reinterpret_cast<const unsigned long long*>(&Bst[tx][k2 * 2]);
            #pragma unroll
            for (int r = 0; r < 8; r++) {
                unsigned long long av =
                    *reinterpret_cast<const unsigned long long*>(&As[ty * 8 + r][k2 * 2]);
                acc2[r] = fma2(av, bv, acc2[r]);
            }
        }
        float asv = as1[cb * HID + tx];
        float adv = ad1[cb * HID + tx];
        #pragma unroll
        for (int r = 0; r < 8; r++) {
            float acc = pairsum(acc2[r]);
            int gr = row0 + ty * 8 + r;
            if (gr < NN) g_h1h[(size_t)gr * F1 + cb * 32 + tx] = __float2half_rn(acc);
            float sv = acc * asv;
            float dv = acc * adv;
            #pragma unroll
            for (int o = 16; o; o >>= 1) {
                sv += __shfl_xor_sync(0xffffffffu, sv, o);
                dv += __shfl_xor_sync(0xffffffffu, dv, o);
            }
            if (tx == 0 && gr < NN) {
                g_asrc1[gr * HEADS + cb] = sv;
                g_adst1[gr * HEADS + cb] = dv;
            }
        }
    }
}

// ---------------- aggregate layer 1 (fp16 gather) ----------------
__global__ void aggregate1(const float* __restrict__ b1) {
    int n = (blockIdx.x * blockDim.x + threadIdx.x) >> 5;
    if (n >= NN) return;
    int lane = threadIdx.x & 31;
    int beg = g_rowstart[n];
    int end = beg + g_count[n] + 1;
    int h4 = lane & 3;
    float adst = (lane < 16) ? g_adst1[n * HEADS + h4] : 0.f;
    float denp = 0.f;
    float4 acc = make_float4(0.f, 0.f, 0.f, 0.f);
    int hh = lane >> 3;
    int j = beg;
    for (; j + 4 <= end; j += 4) {
        int sK = (lane < 4) ? __float_as_int(g_sb[j + lane].y) : 0;
        int s0 = __shfl_sync(0xffffffffu, sK, 0);
        int s1 = __shfl_sync(0xffffffffu, sK, 1);
        int s2 = __shfl_sync(0xffffffffu, sK, 2);
        int s3 = __shfl_sync(0xffffffffu, sK, 3);
        float ex = 0.f;
        if (lane < 16) {
            int k = lane >> 2;
            int sk = (k == 0) ? s0 : (k == 1) ? s1 : (k == 2) ? s2 : s3;
            float aed = ((const float*)&g_saed1[j + k])[h4];
            float lg = g_asrc1[sk * HEADS + h4] + adst + aed;
            lg = (lg > 0.f) ? lg : NEG_SLOPE * lg;
            ex = __expf(lg);
            denp += ex;
        }
        float e0 = __shfl_sync(0xffffffffu, ex, hh);
        float e1 = __shfl_sync(0xffffffffu, ex, 4 + hh);
        float e2 = __shfl_sync(0xffffffffu, ex, 8 + hh);
        float e3 = __shfl_sync(0xffffffffu, ex, 12 + hh);
        float4 v0 = gather_h4(&g_h1h[(size_t)s0 * F1 + lane * 4]);
        float4 v1 = gather_h4(&g_h1h[(size_t)s1 * F1 + lane * 4]);
        float4 v2 = gather_h4(&g_h1h[(size_t)s2 * F1 + lane * 4]);
        float4 v3 = gather_h4(&g_h1h[(size_t)s3 * F1 + lane * 4]);
        acc.x += e0 * v0.x + e1 * v1.x + e2 * v2.x + e3 * v3.x;
        acc.y += e0 * v0.y + e1 * v1.y + e2 * v2.y + e3 * v3.y;
        acc.z += e0 * v0.z + e1 * v1.z + e2 * v2.z + e3 * v3.z;
        acc.w += e0 * v0.w + e1 * v1.w + e2 * v2.w + e3 * v3.w;
    }
    for (; j < end; j++) {
        float2 sb = g_sb[j];
        int se = __float_as_int(sb.y);
        float ex = 0.f;
        if (lane < 4) {
            float aed = ((const float*)&g_saed1[j])[lane];
            float lg = g_asrc1[se * HEADS + lane] + adst + aed;
            lg = (lg > 0.f) ? lg : NEG_SLOPE * lg;
            ex = __expf(lg);
            denp += ex;
        }
        float eb = __shfl_sync(0xffffffffu, ex, hh);
        float4 v = gather_h4(&g_h1h[(size_t)se * F1 + lane * 4]);
        acc.x += eb * v.x;
        acc.y += eb * v.y;
        acc.z += eb * v.z;
        acc.w += eb * v.w;
    }
    float den = __shfl_sync(0xffffffffu, denp, hh)
              + __shfl_sync(0xffffffffu, denp, 4 + hh)
              + __shfl_sync(0xffffffffu, denp, 8 + hh)
              + __shfl_sync(0xffffffffu, denp, 12 + hh);
    float inv = 1.f / (den + 1e-16f);
    float4 bv = *reinterpret_cast<const float4*>(&b1[lane * 4]);
    float4 o;
    o.x = fmaxf(acc.x * inv + bv.x, 0.f);
    o.y = fmaxf(acc.y * inv + bv.y, 0.f);
    o.z = fmaxf(acc.z * inv + bv.z, 0.f);
    o.w = fmaxf(acc.w * inv + bv.w, 0.f);
    *reinterpret_cast<float4*>(&g_hr[(size_t)n * F1 + lane * 4]) = o;
}

// ---------------- GEMM2 (FFMA2): h2(fp16) = hr @ W2, fused coef2 ----------------
__global__ void gemm2(const float* __restrict__ B,
                      const float* __restrict__ as2, const float* __restrict__ ad2) {
    __shared__ float As[64][F1 + 4];
    __shared__ float Bst[32][F1 + 4];
    int row0 = blockIdx.x * 64;
    int tx = threadIdx.x & 31;
    int ty = threadIdx.x >> 5;
    {
        const float4* A4 = reinterpret_cast<const float4*>(g_hr);
        #pragma unroll
        for (int i = 0; i < 8; i++) {
            int idx = threadIdx.x + i * 256;
            int r = idx >> 5, c4 = idx & 31;
            int gr = row0 + r;
            float4 v = (gr < NN) ? A4[(size_t)gr * 32 + c4] : make_float4(0.f, 0.f, 0.f, 0.f);
            *reinterpret_cast<float4*>(&As[r][c4 * 4]) = v;
        }
    }
    #pragma unroll
    for (int i = 0; i < 16; i++) {
        int idx = threadIdx.x + i * 256;
        int r = idx >> 5, c = idx & 31;
        Bst[c][r] = B[(size_t)r * OUTF + c];
    }
    __syncthreads();
    unsigned long long acc2[8];
    #pragma unroll
    for (int r = 0; r < 8; r++) acc2[r] = 0ull;
    #pragma unroll 4
    for (int k2 = 0; k2 < F1 / 2; k2++) {
        unsigned long long bv = *reinterpret_cast<const unsigned long long*>(&Bst[tx][k2 * 2]);
        #pragma unroll
        for (int r = 0; r < 8; r++) {
            unsigned long long av =
                *reinterpret_cast<const unsigned long long*>(&As[ty * 8 + r][k2 * 2]);
            acc2[r] = fma2(av, bv, acc2[r]);
        }
    }
    float asv = as2[tx];
    float adv = ad2[tx];
    #pragma unroll
    for (int r = 0; r < 8; r++) {
        float acc = pairsum(acc2[r]);
        int gr = row0 + ty * 8 + r;
        if (gr < NN) g_h2h[(size_t)gr * OUTF + tx] = __float2half_rn(acc);
        float sv = acc * asv;
        float dv = acc * adv;
        #pragma unroll
        for (int o = 16; o; o >>= 1) {
            sv += __shfl_xor_sync(0xffffffffu, sv, o);
            dv += __shfl_xor_sync(0xffffffffu, dv, o);
        }
        if (tx == 0 && gr < NN) {
            g_asrc2[gr] = sv;
            g_adst2[gr] = dv;
        }
    }
}

// ---------------- aggregate layer 2 (fp16 gather) ----------------
__global__ void aggregate2(float* __restrict__ out, const float* __restrict__ b2) {
    int n = (blockIdx.x * blockDim.x + threadIdx.x) >> 5;
    if (n >= NN) return;
    int lane = threadIdx.x & 31;
    int beg = g_rowstart[n];
    int end = beg + g_count[n] + 1;
    float adst = g_adst2[n];
    float denp = 0.f, acc = 0.f;
    int j = beg;
    for (; j + 4 <= end; j += 4) {
        int sK = 0;
        float ex = 0.f;
        if (lane < 4) {
            float2 sbv = g_sb[j + lane];
            sK = __float_as_int(sbv.y);
            float lg = g_asrc2[sK] + adst + sbv.x;
            lg = (lg > 0.f) ? lg : NEG_SLOPE * lg;
            ex = __expf(lg);
            denp += ex;
        }
        int s0 = __shfl_sync(0xffffffffu, sK, 0);
        int s1 = __shfl_sync(0xffffffffu, sK, 1);
        int s2 = __shfl_sync(0xffffffffu, sK, 2);
        int s3 = __shfl_sync(0xffffffffu, sK, 3);
        float e0 = __shfl_sync(0xffffffffu, ex, 0);
        float e1 = __shfl_sync(0xffffffffu, ex, 1);
        float e2 = __shfl_sync(0xffffffffu, ex, 2);
        float e3 = __shfl_sync(0xffffffffu, ex, 3);
        acc += e0 * __half2float(g_h2h[(size_t)s0 * OUTF + lane])
             + e1 * __half2float(g_h2h[(size_t)s1 * OUTF + lane])
             + e2 * __half2float(g_h2h[(size_t)s2 * OUTF + lane])
             + e3 * __half2float(g_h2h[(size_t)s3 * OUTF + lane]);
    }
    for (; j < end; j++) {
        float2 sb = g_sb[j];
        int se = __float_as_int(sb.y);
        float ex = 0.f;
        if (lane == 0) {
            float lg = g_asrc2[se] + adst + sb.x;
            lg = (lg > 0.f) ? lg : NEG_SLOPE * lg;
            ex = __expf(lg);
            denp += ex;
        }
        float eb = __shfl_sync(0xffffffffu, ex, 0);
        acc += eb * __half2float(g_h2h[(size_t)se * OUTF + lane]);
    }
    float den = __shfl_sync(0xffffffffu, denp, 0)
              + __shfl_sync(0xffffffffu, denp, 1)
              + __shfl_sync(0xffffffffu, denp, 2)
              + __shfl_sync(0xffffffffu, denp, 3);
    out[(size_t)n * OUTF + lane] = acc / (den + 1e-16f) + b2[lane];
}

// ---------------- launch ----------------
extern "C" void kernel_launch(void* const* d_in, const int* in_sizes, int n_in,
                              void* d_out, int out_size) {
    int used[64];
    for (int i = 0; i < n_in && i < 64; i++) used[i] = 0;
    auto take = [&](int want) -> const void* {
        for (int i = 0; i < n_in && i < 64; i++)
            if (!used[i] && in_sizes[i] == want) { used[i] = 1; return d_in[i]; }
        return nullptr;
    };
    const float* x   = (const float*)take(NN * IN_F);
    const void*  eix = take(2 * EE);
    const float* ea  = (const float*)take(EE * ED_F);
    const float* W1  = (const float*)take(IN_F * F1);
    const float* We1 = (const float*)take(ED_F * F1);
    const float* W2  = (const float*)take(F1 * OUTF);
    const float* We2 = (const float*)take(ED_F * OUTF);
    const float* g128[4] = {nullptr, nullptr, nullptr, nullptr};
    const float* g32[4]  = {nullptr, nullptr, nullptr, nullptr};
    int n128 = 0, n32 = 0;
    for (int i = 0; i < n_in && i < 64; i++) {
        if (used[i]) continue;
        if (in_sizes[i] == 128 && n128 < 4) g128[n128++] = (const float*)d_in[i];
        else if (in_sizes[i] == 32 && n32 < 4) g32[n32++] = (const float*)d_in[i];
    }
    const float* as1 = g128[0], *ad1 = g128[1], *ae1 = g128[2], *b1 = g128[3];
    const float* as2 = g32[0],  *ad2 = g32[1],  *ae2 = g32[2],  *b2 = g32[3];
    if (!x || !eix || !ea || !W1 || !We1 || !W2 || !We2 || n128 < 4 || n32 < 4) {
        x   = (const float*)d_in[0];  eix = d_in[1];               ea  = (const float*)d_in[2];
        W1  = (const float*)d_in[3];  We1 = (const float*)d_in[4];
        as1 = (const float*)d_in[5];  ad1 = (const float*)d_in[6]; ae1 = (const float*)d_in[7];
        b1  = (const float*)d_in[8];  W2  = (const float*)d_in[9]; We2 = (const float*)d_in[10];
        as2 = (const float*)d_in[11]; ad2 = (const float*)d_in[12]; ae2 = (const float*)d_in[13];
        b2  = (const float*)d_in[14];
    }
    float* out = (float*)d_out;

    const int TB = 256;

    setup<<<(NN + TB - 1) / TB, TB>>>(eix, We1, ae1, We2, ae2);
    count_edges<<<(EE + TB * 4 - 1) / (TB * 4), TB>>>(eix);
    assign_rows<<<(NN + TB - 1) / TB, TB>>>();
    edge_dots_scatter<<<(EE + TB - 1) / TB, TB>>>(eix, ea);
    selfloop_fill<<<(NN + TB - 1) / TB, TB>>>();

    gemm1<<<(NN + 63) / 64, TB>>>(x, W1, as1, ad1);
    aggregate1<<<(int)(((size_t)NN * 32 + TB - 1) / TB), TB>>>(b1);

    gemm2<<<(NN + 63) / 64, TB>>>(W2, as2, ad2);
    aggregate2<<<(int)(((size_t)NN * 32 + TB - 1) / TB), TB>>>(out, b2);
}

// round 15
// speedup vs baseline: 1.1797x; 1.0184x over previous
#include <cuda_runtime.h>
#include <cuda_fp16.h>
#include <cstdint>

#define NN 50000
#define EE 800000
#define E2T (EE + NN)
#define IN_F 128
#define ED_F 16
#define F1 128
#define HEADS 4
#define HID 32
#define OUTF 32
#define NEG_SLOPE 0.2f

// ---------------- scratch ----------------
__device__ __align__(16) __half g_h1h[(size_t)NN * F1];   // layer1 features (fp16 gather source)
__device__ __align__(16) float g_hr[(size_t)NN * F1];     // layer1 aggregated+relu (fp32)
__device__ __align__(16) __half g_h2h[(size_t)NN * OUTF]; // layer2 features (fp16 gather source)
__device__ __align__(16) float4 g_rec[(size_t)E2T * 2];   // 32B/edge: [aed1][aed2,src,_,_]
__device__ int      g_count[NN];
__device__ int      g_rowstart[NN];
__device__ int      g_cursor[NN];
__device__ int      g_total;
__device__ float    g_asrc1[NN * HEADS], g_adst1[NN * HEADS];
__device__ float    g_asrc2[NN], g_adst2[NN];
__device__ float    g_wae1[ED_F * HEADS];
__device__ float    g_wae2[ED_F];
__device__ float    g_emean[ED_F];
__device__ int      g_is64;

__device__ __forceinline__ void load_edge(const void* eidx, int e, int is64, int& se, int& de) {
    if (is64) {
        const long long* p = (const long long*)eidx;
        se = (int)p[e];
        de = (int)p[(size_t)EE + e];
    } else {
        const int* p = (const int*)eidx;
        se = p[e];
        de = p[EE + e];
    }
}

__device__ __forceinline__ unsigned long long fma2(unsigned long long a, unsigned long long b,
                                                   unsigned long long c) {
    unsigned long long d;
    asm("fma.rn.f32x2 %0, %1, %2, %3;" : "=l"(d) : "l"(a), "l"(b), "l"(c));
    return d;
}
__device__ __forceinline__ float pairsum(unsigned long long v) {
    float lo, hi;
    asm("mov.b64 {%0, %1}, %2;" : "=f"(lo), "=f"(hi) : "l"(v));
    return lo + hi;
}
__device__ __forceinline__ float4 gather_h4(const __half* p) {
    uint2 u = *reinterpret_cast<const uint2*>(p);
    __half2 a = *reinterpret_cast<__half2*>(&u.x);
    __half2 b = *reinterpret_cast<__half2*>(&u.y);
    float2 fa = __half22float2(a);
    float2 fb = __half22float2(b);
    return make_float4(fa.x, fa.y, fb.x, fb.y);
}

// ---------------- setup ----------------
__global__ void setup(const void* eidx,
                      const float* __restrict__ We1, const float* __restrict__ ae1,
                      const float* __restrict__ We2, const float* __restrict__ ae2) {
    int i = blockIdx.x * blockDim.x + threadIdx.x;
    if (i < NN) g_count[i] = 0;
    if (i < ED_F) g_emean[i] = 0.f;
    if (i == 0) g_total = 0;
    if (blockIdx.x == 0 && threadIdx.x < 32) {
        const int* p = (const int*)eidx;
        int lane = threadIdx.x;
        int allzero = 1;
        #pragma unroll
        for (int k = 0; k < 8; k++)
            if (p[2 * (lane * 8 + k) + 1] != 0) allzero = 0;
        unsigned vote = __ballot_sync(0xffffffffu, allzero);
        if (lane == 0) g_is64 = (vote == 0xffffffffu) ? 1 : 0;
    }
    if (blockIdx.x == 1) {
        int t = threadIdx.x;
        if (t < ED_F * HEADS) {
            int d = t >> 2, h = t & 3;
            float s = 0.f;
            #pragma unroll
            for (int c = 0; c < HID; c++) s += We1[d * F1 + h * HID + c] * ae1[h * HID + c];
            g_wae1[t] = s;
        } else if (t < ED_F * HEADS + ED_F) {
            int d = t - ED_F * HEADS;
            float s = 0.f;
            #pragma unroll
            for (int c = 0; c < OUTF; c++) s += We2[d * OUTF + c] * ae2[c];
            g_wae2[d] = s;
        }
    }
}

// ---------------- CSR count ----------------
__global__ void count_edges(const void* __restrict__ eidx) {
    int base = 4 * (blockIdx.x * blockDim.x + threadIdx.x);
    int is64 = g_is64;
    #pragma unroll
    for (int i = 0; i < 4; i++) {
        int e = base + i;
        if (e < EE) {
            int de;
            if (is64) de = (int)((const long long*)eidx)[(size_t)EE + e];
            else      de = ((const int*)eidx)[EE + e];
            atomicAdd(&g_count[de], 1);
        }
    }
}

// ---------------- parallel segment assignment ----------------
__global__ void assign_rows() {
    __shared__ int sh[256];
    __shared__ int sbase;
    int tid = threadIdx.x;
    int n = blockIdx.x * 256 + tid;
    int deg = (n < NN) ? g_count[n] + 1 : 0;
    sh[tid] = deg;
    __syncthreads();
    #pragma unroll
    for (int o = 1; o < 256; o <<= 1) {
        int v = (tid >= o) ? sh[tid - o] : 0;
        __syncthreads();
        sh[tid] += v;
        __syncthreads();
    }
    int incl = sh[tid];
    if (tid == 255) sbase = atomicAdd(&g_total, incl);
    __syncthreads();
    if (n < NN) {
        int rs = sbase + incl - deg;
        g_rowstart[n] = rs;
        g_cursor[n] = rs + 1;   // slot 0 reserved for self-loop
    }
}

// ---------------- edge dots + CSR scatter + emean ----------------
__global__ void edge_dots_scatter(const void* __restrict__ eidx, const float* __restrict__ ea) {
    __shared__ float4 swae1[ED_F];
    __shared__ float  swae2[ED_F];
    __shared__ float  s16[ED_F];
    if (threadIdx.x < ED_F) {
        swae1[threadIdx.x] = *reinterpret_cast<const float4*>(&g_wae1[threadIdx.x * HEADS]);
        swae2[threadIdx.x] = g_wae2[threadIdx.x];
        s16[threadIdx.x] = 0.f;
    }
    __syncthreads();
    int e = blockIdx.x * blockDim.x + threadIdx.x;
    float4 q[4];
    if (e < EE) {
        const float4* eav = reinterpret_cast<const float4*>(ea + (size_t)e * ED_F);
        #pragma unroll
        for (int i = 0; i < 4; i++) q[i] = eav[i];
        float a0 = 0.f, a1 = 0.f, a2 = 0.f, a3 = 0.f, a4 = 0.f;
        #pragma unroll
        for (int i = 0; i < 4; i++) {
            const float* v = &q[i].x;
            #pragma unroll
            for (int j = 0; j < 4; j++) {
                int d = i * 4 + j;
                float vv = v[j];
                float4 w = swae1[d];
                a0 += vv * w.x;
                a1 += vv * w.y;
                a2 += vv * w.z;
                a3 += vv * w.w;
                a4 += vv * swae2[d];
            }
        }
        int se, de;
        load_edge(eidx, e, g_is64, se, de);
        int pos = atomicAdd(&g_cursor[de], 1);
        g_rec[2 * (size_t)pos]     = make_float4(a0, a1, a2, a3);
        g_rec[2 * (size_t)pos + 1] = make_float4(a4, __int_as_float(se), 0.f, 0.f);
    } else {
        #pragma unroll
        for (int i = 0; i < 4; i++) q[i] = make_float4(0.f, 0.f, 0.f, 0.f);
    }
    #pragma unroll
    for (int o = 16; o; o >>= 1) {
        #pragma unroll
        for (int i = 0; i < 4; i++) {
            q[i].x += __shfl_xor_sync(0xffffffffu, q[i].x, o);
            q[i].y += __shfl_xor_sync(0xffffffffu, q[i].y, o);
            q[i].z += __shfl_xor_sync(0xffffffffu, q[i].z, o);
            q[i].w += __shfl_xor_sync(0xffffffffu, q[i].w, o);
        }
    }
    if ((threadIdx.x & 31) == 0) {
        #pragma unroll
        for (int i = 0; i < 4; i++) {
            atomicAdd(&s16[i * 4 + 0], q[i].x);
            atomicAdd(&s16[i * 4 + 1], q[i].y);
            atomicAdd(&s16[i * 4 + 2], q[i].z);
            atomicAdd(&s16[i * 4 + 3], q[i].w);
        }
    }
    __syncthreads();
    if (threadIdx.x < ED_F) atomicAdd(&g_emean[threadIdx.x], s16[threadIdx.x]);
}

// ---------------- self-loop fill ----------------
__global__ void selfloop_fill() {
    __shared__ float sl1s[HEADS];
    __shared__ float sl2s;
    int t = threadIdx.x;
    const float inv_e = 1.f / (float)EE;
    if (t < HEADS) {
        float s = 0.f;
        #pragma unroll
        for (int d = 0; d < ED_F; d++) s += g_emean[d] * inv_e * g_wae1[d * HEADS + t];
        sl1s[t] = s;
    } else if (t == HEADS) {
        float s = 0.f;
        #pragma unroll
        for (int d = 0; d < ED_F; d++) s += g_emean[d] * inv_e * g_wae2[d];
        sl2s = s;
    }
    __syncthreads();
    int n = blockIdx.x * blockDim.x + t;
    if (n >= NN) return;
    int j = g_rowstart[n];
    g_rec[2 * (size_t)j]     = make_float4(sl1s[0], sl1s[1], sl1s[2], sl1s[3]);
    g_rec[2 * (size_t)j + 1] = make_float4(sl2s, __int_as_float(n), 0.f, 0.f);
}

// ---------------- GEMM1 (FFMA2, conflict-free Bst): h1(fp16) = x @ W1, fused coef1 ----------------
__global__ void gemm1(const float* __restrict__ A, const float* __restrict__ B,
                      const float* __restrict__ as1, const float* __restrict__ ad1) {
    __shared__ float As[64][IN_F + 4];    // float4 stores -> 16B-aligned stride (132)
    __shared__ float Bst[32][IN_F + 2];   // 8B loads only -> stride 130 (2-phase, no 8-way conflict)
    int row0 = blockIdx.x * 64;
    int tx = threadIdx.x & 31;
    int ty = threadIdx.x >> 5;
    {
        const float4* A4 = reinterpret_cast<const float4*>(A);
        #pragma unroll
        for (int i = 0; i < 8; i++) {
            int idx = threadIdx.x + i * 256;
            int r = idx >> 5, c4 = idx & 31;
            int gr = row0 + r;
            float4 v = (gr < NN) ? A4[(size_t)gr * 32 + c4] : make_float4(0.f, 0.f, 0.f, 0.f);
            *reinterpret_cast<float4*>(&As[r][c4 * 4]) = v;
        }
    }
    for (int cb = 0; cb < HEADS; cb++) {
        __syncthreads();
        #pragma unroll
        for (int i = 0; i < 16; i++) {
            int idx = threadIdx.x + i * 256;
            int r = idx >> 5, c = idx & 31;
            Bst[c][r] = B[(size_t)r * F1 + cb * 32 + c];
        }
        __syncthreads();
        unsigned long long acc2[8];
        #pragma unroll
        for (int r = 0; r < 8; r++) acc2[r] = 0ull;
        #pragma unroll 4
        for (int k2 = 0; k2 < IN_F / 2; k2++) {
            unsigned long long bv = *reinterpret_cast<const unsigned long long*>(&Bst[tx][k2 * 2]);
            #pragma unroll
            for (int r = 0; r < 8; r++) {
                unsigned long long av =
                    *reinterpret_cast<const unsigned long long*>(&As[ty * 8 + r][k2 * 2]);
                acc2[r] = fma2(av, bv, acc2[r]);
            }
        }
        float asv = as1[cb * HID + tx];
        float adv = ad1[cb * HID + tx];
        #pragma unroll
        for (int r = 0; r < 8; r++) {
            float acc = pairsum(acc2[r]);
            int gr = row0 + ty * 8 + r;
            if (gr < NN) g_h1h[(size_t)gr * F1 + cb * 32 + tx] = __float2half_rn(acc);
            float sv = acc * asv;
            float dv = acc * adv;
            #pragma unroll
            for (int o = 16; o; o >>= 1) {
                sv += __shfl_xor_sync(0xffffffffu, sv, o);
                dv += __shfl_xor_sync(0xffffffffu, dv, o);
            }
            if (tx == 0 && gr < NN) {
                g_asrc1[gr * HEADS + cb] = sv;
                g_adst1[gr * HEADS + cb] = dv;
            }
        }
    }
}

// ---------------- aggregate layer 1 (fp16 gather, packed records) ----------------
__global__ void aggregate1(const float* __restrict__ b1) {
    int n = (blockIdx.x * blockDim.x + threadIdx.x) >> 5;
    if (n >= NN) return;
    int lane = threadIdx.x & 31;
    int beg = g_rowstart[n];
    int end = beg + g_count[n] + 1;
    int h4 = lane & 3;
    float adst = (lane < 16) ? g_adst1[n * HEADS + h4] : 0.f;
    float denp = 0.f;
    float4 acc = make_float4(0.f, 0.f, 0.f, 0.f);
    int hh = lane >> 3;
    int j = beg;
    for (; j + 4 <= end; j += 4) {
        int sK = (lane < 4)
            ? __float_as_int(reinterpret_cast<const float2*>(&g_rec[2 * (size_t)(j + lane) + 1])->y)
            : 0;
        int s0 = __shfl_sync(0xffffffffu, sK, 0);
        int s1 = __shfl_sync(0xffffffffu, sK, 1);
        int s2 = __shfl_sync(0xffffffffu, sK, 2);
        int s3 = __shfl_sync(0xffffffffu, sK, 3);
        float ex = 0.f;
        if (lane < 16) {
            int k = lane >> 2;
            int sk = (k == 0) ? s0 : (k == 1) ? s1 : (k == 2) ? s2 : s3;
            float aed = ((const float*)&g_rec[2 * (size_t)(j + k)])[h4];
            float lg = g_asrc1[sk * HEADS + h4] + adst + aed;
            lg = (lg > 0.f) ? lg : NEG_SLOPE * lg;
            ex = __expf(lg);
            denp += ex;
        }
        float e0 = __shfl_sync(0xffffffffu, ex, hh);
        float e1 = __shfl_sync(0xffffffffu, ex, 4 + hh);
        float e2 = __shfl_sync(0xffffffffu, ex, 8 + hh);
        float e3 = __shfl_sync(0xffffffffu, ex, 12 + hh);
        float4 v0 = gather_h4(&g_h1h[(size_t)s0 * F1 + lane * 4]);
        float4 v1 = gather_h4(&g_h1h[(size_t)s1 * F1 + lane * 4]);
        float4 v2 = gather_h4(&g_h1h[(size_t)s2 * F1 + lane * 4]);
        float4 v3 = gather_h4(&g_h1h[(size_t)s3 * F1 + lane * 4]);
        acc.x += e0 * v0.x + e1 * v1.x + e2 * v2.x + e3 * v3.x;
        acc.y += e0 * v0.y + e1 * v1.y + e2 * v2.y + e3 * v3.y;
        acc.z += e0 * v0.z + e1 * v1.z + e2 * v2.z + e3 * v3.z;
        acc.w += e0 * v0.w + e1 * v1.w + e2 * v2.w + e3 * v3.w;
    }
    for (; j < end; j++) {
        float2 sb = *reinterpret_cast<const float2*>(&g_rec[2 * (size_t)j + 1]);
        int se = __float_as_int(sb.y);
        float ex = 0.f;
        if (lane < 4) {
            float aed = ((const float*)&g_rec[2 * (size_t)j])[lane];
            float lg = g_asrc1[se * HEADS + lane] + adst + aed;
            lg = (lg > 0.f) ? lg : NEG_SLOPE * lg;
            ex = __expf(lg);
            denp += ex;
        }
        float eb = __shfl_sync(0xffffffffu, ex, hh);
        float4 v = gather_h4(&g_h1h[(size_t)se * F1 + lane * 4]);
        acc.x += eb * v.x;
        acc.y += eb * v.y;
        acc.z += eb * v.z;
        acc.w += eb * v.w;
    }
    float den = __shfl_sync(0xffffffffu, denp, hh)
              + __shfl_sync(0xffffffffu, denp, 4 + hh)
              + __shfl_sync(0xffffffffu, denp, 8 + hh)
              + __shfl_sync(0xffffffffu, denp, 12 + hh);
    float inv = 1.f / (den + 1e-16f);
    float4 bv = *reinterpret_cast<const float4*>(&b1[lane * 4]);
    float4 o;
    o.x = fmaxf(acc.x * inv + bv.x, 0.f);
    o.y = fmaxf(acc.y * inv + bv.y, 0.f);
    o.z = fmaxf(acc.z * inv + bv.z, 0.f);
    o.w = fmaxf(acc.w * inv + bv.w, 0.f);
    *reinterpret_cast<float4*>(&g_hr[(size_t)n * F1 + lane * 4]) = o;
}

// ---------------- GEMM2 (FFMA2, conflict-free Bst): h2(fp16) = hr @ W2, fused coef2 ----------------
__global__ void gemm2(const float* __restrict__ B,
                      const float* __restrict__ as2, const float* __restrict__ ad2) {
    __shared__ float As[64][F1 + 4];
    __shared__ float Bst[32][F1 + 2];   // stride 130
    int row0 = blockIdx.x * 64;
    int tx = threadIdx.x & 31;
    int ty = threadIdx.x >> 5;
    {
        const float4* A4 = reinterpret_cast<const float4*>(g_hr);
        #pragma unroll
        for (int i = 0; i < 8; i++) {
            int idx = threadIdx.x + i * 256;
            int r = idx >> 5, c4 = idx & 31;
            int gr = row0 + r;
            float4 v = (gr < NN) ? A4[(size_t)gr * 32 + c4] : make_float4(0.f, 0.f, 0.f, 0.f);
            *reinterpret_cast<float4*>(&As[r][c4 * 4]) = v;
        }
    }
    #pragma unroll
    for (int i = 0; i < 16; i++) {
        int idx = threadIdx.x + i * 256;
        int r = idx >> 5, c = idx & 31;
        Bst[c][r] = B[(size_t)r * OUTF + c];
    }
    __syncthreads();
    unsigned long long acc2[8];
    #pragma unroll
    for (int r = 0; r < 8; r++) acc2[r] = 0ull;
    #pragma unroll 4
    for (int k2 = 0; k2 < F1 / 2; k2++) {
        unsigned long long bv = *reinterpret_cast<const unsigned long long*>(&Bst[tx][k2 * 2]);
        #pragma unroll
        for (int r = 0; r < 8; r++) {
            unsigned long long av =
                *reinterpret_cast<const unsigned long long*>(&As[ty * 8 + r][k2 * 2]);
            acc2[r] = fma2(av, bv, acc2[r]);
        }
    }
    float asv = as2[tx];
    float adv = ad2[tx];
    #pragma unroll
    for (int r = 0; r < 8; r++) {
        float acc = pairsum(acc2[r]);
        int gr = row0 + ty * 8 + r;
        if (gr < NN) g_h2h[(size_t)gr * OUTF + tx] = __float2half_rn(acc);
        float sv = acc * asv;
        float dv = acc * adv;
        #pragma unroll
        for (int o = 16; o; o >>= 1) {
            sv += __shfl_xor_sync(0xffffffffu, sv, o);
            dv += __shfl_xor_sync(0xffffffffu, dv, o);
        }
        if (tx == 0 && gr < NN) {
            g_asrc2[gr] = sv;
            g_adst2[gr] = dv;
        }
    }
}

// ---------------- aggregate layer 2 (fp16 gather, packed records) ----------------
__global__ void aggregate2(float* __restrict__ out, const float* __restrict__ b2) {
    int n = (blockIdx.x * blockDim.x + threadIdx.x) >> 5;
    if (n >= NN) return;
    int lane = threadIdx.x & 31;
    int beg = g_rowstart[n];
    int end = beg + g_count[n] + 1;
    float adst = g_adst2[n];
    float denp = 0.f, acc = 0.f;
    int j = beg;
    for (; j + 4 <= end; j += 4) {
        int sK = 0;
        float ex = 0.f;
        if (lane < 4) {
            float2 sbv = *reinterpret_cast<const float2*>(&g_rec[2 * (size_t)(j + lane) + 1]);
            sK = __float_as_int(sbv.y);
            float lg = g_asrc2[sK] + adst + sbv.x;
            lg = (lg > 0.f) ? lg : NEG_SLOPE * lg;
            ex = __expf(lg);
            denp += ex;
        }
        int s0 = __shfl_sync(0xffffffffu, sK, 0);
        int s1 = __shfl_sync(0xffffffffu, sK, 1);
        int s2 = __shfl_sync(0xffffffffu, sK, 2);
        int s3 = __shfl_sync(0xffffffffu, sK, 3);
        float e0 = __shfl_sync(0xffffffffu, ex, 0);
        float e1 = __shfl_sync(0xffffffffu, ex, 1);
        float e2 = __shfl_sync(0xffffffffu, ex, 2);
        float e3 = __shfl_sync(0xffffffffu, ex, 3);
        acc += e0 * __half2float(g_h2h[(size_t)s0 * OUTF + lane])
             + e1 * __half2float(g_h2h[(size_t)s1 * OUTF + lane])
             + e2 * __half2float(g_h2h[(size_t)s2 * OUTF + lane])
             + e3 * __half2float(g_h2h[(size_t)s3 * OUTF + lane]);
    }
    for (; j < end; j++) {
        float2 sb = *reinterpret_cast<const float2*>(&g_rec[2 * (size_t)j + 1]);
        int se = __float_as_int(sb.y);
        float ex = 0.f;
        if (lane == 0) {
            float lg = g_asrc2[se] + adst + sb.x;
            lg = (lg > 0.f) ? lg : NEG_SLOPE * lg;
            ex = __expf(lg);
            denp += ex;
        }
        float eb = __shfl_sync(0xffffffffu, ex, 0);
        acc += eb * __half2float(g_h2h[(size_t)se * OUTF + lane]);
    }
    float den = __shfl_sync(0xffffffffu, denp, 0)
              + __shfl_sync(0xffffffffu, denp, 1)
              + __shfl_sync(0xffffffffu, denp, 2)
              + __shfl_sync(0xffffffffu, denp, 3);
    out[(size_t)n * OUTF + lane] = acc / (den + 1e-16f) + b2[lane];
}

// ---------------- launch ----------------
extern "C" void kernel_launch(void* const* d_in, const int* in_sizes, int n_in,
                              void* d_out, int out_size) {
    int used[64];
    for (int i = 0; i < n_in && i < 64; i++) used[i] = 0;
    auto take = [&](int want) -> const void* {
        for (int i = 0; i < n_in && i < 64; i++)
            if (!used[i] && in_sizes[i] == want) { used[i] = 1; return d_in[i]; }
        return nullptr;
    };
    const float* x   = (const float*)take(NN * IN_F);
    const void*  eix = take(2 * EE);
    const float* ea  = (const float*)take(EE * ED_F);
    const float* W1  = (const float*)take(IN_F * F1);
    const float* We1 = (const float*)take(ED_F * F1);
    const float* W2  = (const float*)take(F1 * OUTF);
    const float* We2 = (const float*)take(ED_F * OUTF);
    const float* g128[4] = {nullptr, nullptr, nullptr, nullptr};
    const float* g32[4]  = {nullptr, nullptr, nullptr, nullptr};
    int n128 = 0, n32 = 0;
    for (int i = 0; i < n_in && i < 64; i++) {
        if (used[i]) continue;
        if (in_sizes[i] == 128 && n128 < 4) g128[n128++] = (const float*)d_in[i];
        else if (in_sizes[i] == 32 && n32 < 4) g32[n32++] = (const float*)d_in[i];
    }
    const float* as1 = g128[0], *ad1 = g128[1], *ae1 = g128[2], *b1 = g128[3];
    const float* as2 = g32[0],  *ad2 = g32[1],  *ae2 = g32[2],  *b2 = g32[3];
    if (!x || !eix || !ea || !W1 || !We1 || !W2 || !We2 || n128 < 4 || n32 < 4) {
        x   = (const float*)d_in[0];  eix = d_in[1];               ea  = (const float*)d_in[2];
        W1  = (const float*)d_in[3];  We1 = (const float*)d_in[4];
        as1 = (const float*)d_in[5];  ad1 = (const float*)d_in[6]; ae1 = (const float*)d_in[7];
        b1  = (const float*)d_in[8];  W2  = (const float*)d_in[9]; We2 = (const float*)d_in[10];
        as2 = (const float*)d_in[11]; ad2 = (const float*)d_in[12]; ae2 = (const float*)d_in[13];
        b2  = (const float*)d_in[14];
    }
    float* out = (float*)d_out;

    const int TB = 256;

    // one-time stream/event creation (no device memory involved)
    static cudaStream_t s2 = nullptr;
    static cudaEvent_t e1 = nullptr, e2 = nullptr;
    if (!s2) {
        cudaStreamCreateWithFlags(&s2, cudaStreamNonBlocking);
        cudaEventCreateWithFlags(&e1, cudaEventDisableTiming);
        cudaEventCreateWithFlags(&e2, cudaEventDisableTiming);
    }

    // fork: gemm1 (independent of CSR chain) on s2
    cudaEventRecord(e1, 0);
    cudaStreamWaitEvent(s2, e1, 0);
    gemm1<<<(NN + 63) / 64, TB, 0, s2>>>(x, W1, as1, ad1);
    cudaEventRecord(e2, s2);

    // CSR chain on default stream
    setup<<<(NN + TB - 1) / TB, TB>>>(eix, We1, ae1, We2, ae2);
    count_edges<<<(EE + TB * 4 - 1) / (TB * 4), TB>>>(eix);
    assign_rows<<<(NN + TB - 1) / TB, TB>>>();
    edge_dots_scatter<<<(EE + TB - 1) / TB, TB>>>(eix, ea);
    selfloop_fill<<<(NN + TB - 1) / TB, TB>>>();

    // join
    cudaStreamWaitEvent(0, e2, 0);

    aggregate1<<<(int)(((size_t)NN * 32 + TB - 1) / TB), TB>>>(b1);
    gemm2<<<(NN + 63) / 64, TB>>>(W2, as2, ad2);
    aggregate2<<<(int)(((size_t)NN * 32 + TB - 1) / TB), TB>>>(out, b2);
}

// round 16
// speedup vs baseline: 1.2379x; 1.0494x over previous
#include <cuda_runtime.h>
#include <cuda_fp16.h>
#include <cstdint>

#define NN 50000
#define EE 800000
#define E2T (EE + NN)
#define IN_F 128
#define ED_F 16
#define F1 128
#define HEADS 4
#define HID 32
#define OUTF 32
#define NEG_SLOPE 0.2f
#define FULL 0xffffffffu

// ---------------- scratch ----------------
__device__ __align__(16) __half g_h1h[(size_t)NN * F1];
__device__ __align__(16) float g_hr[(size_t)NN * F1];
__device__ __align__(16) __half g_h2h[(size_t)NN * OUTF];
__device__ __align__(16) float4 g_rec[(size_t)E2T * 2];   // 32B/edge: [aed1][aed2,src,_,_]
__device__ int      g_count[NN];
__device__ int      g_rowstart[NN];
__device__ int      g_cursor[NN];
__device__ int      g_total;
__device__ float    g_asrc1[NN * HEADS], g_adst1[NN * HEADS];
__device__ float    g_asrc2[NN], g_adst2[NN];
__device__ float    g_wae1[ED_F * HEADS];
__device__ float    g_wae2[ED_F];
__device__ float    g_emean[ED_F];
__device__ int      g_is64;

__device__ __forceinline__ void load_edge(const void* eidx, int e, int is64, int& se, int& de) {
    if (is64) {
        const long long* p = (const long long*)eidx;
        se = (int)p[e];
        de = (int)p[(size_t)EE + e];
    } else {
        const int* p = (const int*)eidx;
        se = p[e];
        de = p[EE + e];
    }
}

__device__ __forceinline__ unsigned long long fma2(unsigned long long a, unsigned long long b,
                                                   unsigned long long c) {
    unsigned long long d;
    asm("fma.rn.f32x2 %0, %1, %2, %3;" : "=l"(d) : "l"(a), "l"(b), "l"(c));
    return d;
}
__device__ __forceinline__ float pairsum(unsigned long long v) {
    float lo, hi;
    asm("mov.b64 {%0, %1}, %2;" : "=f"(lo), "=f"(hi) : "l"(v));
    return lo + hi;
}
__device__ __forceinline__ float4 gather_h4(const __half* p) {
    uint2 u = *reinterpret_cast<const uint2*>(p);
    __half2 a = *reinterpret_cast<__half2*>(&u.x);
    __half2 b = *reinterpret_cast<__half2*>(&u.y);
    float2 fa = __half22float2(a);
    float2 fb = __half22float2(b);
    return make_float4(fa.x, fa.y, fb.x, fb.y);
}

// ---------------- setup ----------------
__global__ void setup(const void* eidx,
                      const float* __restrict__ We1, const float* __restrict__ ae1,
                      const float* __restrict__ We2, const float* __restrict__ ae2) {
    int i = blockIdx.x * blockDim.x + threadIdx.x;
    if (i < NN) g_count[i] = 0;
    if (i < ED_F) g_emean[i] = 0.f;
    if (i == 0) g_total = 0;
    if (blockIdx.x == 0 && threadIdx.x < 32) {
        const int* p = (const int*)eidx;
        int lane = threadIdx.x;
        int allzero = 1;
        #pragma unroll
        for (int k = 0; k < 8; k++)
            if (p[2 * (lane * 8 + k) + 1] != 0) allzero = 0;
        unsigned vote = __ballot_sync(FULL, allzero);
        if (lane == 0) g_is64 = (vote == FULL) ? 1 : 0;
    }
    if (blockIdx.x == 1) {
        int t = threadIdx.x;
        if (t < ED_F * HEADS) {
            int d = t >> 2, h = t & 3;
            float s = 0.f;
            #pragma unroll
            for (int c = 0; c < HID; c++) s += We1[d * F1 + h * HID + c] * ae1[h * HID + c];
            g_wae1[t] = s;
        } else if (t < ED_F * HEADS + ED_F) {
            int d = t - ED_F * HEADS;
            float s = 0.f;
            #pragma unroll
            for (int c = 0; c < OUTF; c++) s += We2[d * OUTF + c] * ae2[c];
            g_wae2[d] = s;
        }
    }
}

// ---------------- CSR count ----------------
__global__ void count_edges(const void* __restrict__ eidx) {
    int base = 4 * (blockIdx.x * blockDim.x + threadIdx.x);
    int is64 = g_is64;
    #pragma unroll
    for (int i = 0; i < 4; i++) {
        int e = base + i;
        if (e < EE) {
            int de;
            if (is64) de = (int)((const long long*)eidx)[(size_t)EE + e];
            else      de = ((const int*)eidx)[EE + e];
            atomicAdd(&g_count[de], 1);
        }
    }
}

// ---------------- parallel segment assignment ----------------
__global__ void assign_rows() {
    __shared__ int sh[256];
    __shared__ int sbase;
    int tid = threadIdx.x;
    int n = blockIdx.x * 256 + tid;
    int deg = (n < NN) ? g_count[n] + 1 : 0;
    sh[tid] = deg;
    __syncthreads();
    #pragma unroll
    for (int o = 1; o < 256; o <<= 1) {
        int v = (tid >= o) ? sh[tid - o] : 0;
        __syncthreads();
        sh[tid] += v;
        __syncthreads();
    }
    int incl = sh[tid];
    if (tid == 255) sbase = atomicAdd(&g_total, incl);
    __syncthreads();
    if (n < NN) {
        int rs = sbase + incl - deg;
        g_rowstart[n] = rs;
        g_cursor[n] = rs + 1;
    }
}

// ---------------- edge dots + CSR scatter + emean ----------------
__global__ void edge_dots_scatter(const void* __restrict__ eidx, const float* __restrict__ ea) {
    __shared__ float4 swae1[ED_F];
    __shared__ float  swae2[ED_F];
    __shared__ float  s16[ED_F];
    if (threadIdx.x < ED_F) {
        swae1[threadIdx.x] = *reinterpret_cast<const float4*>(&g_wae1[threadIdx.x * HEADS]);
        swae2[threadIdx.x] = g_wae2[threadIdx.x];
        s16[threadIdx.x] = 0.f;
    }
    __syncthreads();
    int e = blockIdx.x * blockDim.x + threadIdx.x;
    float4 q[4];
    if (e < EE) {
        const float4* eav = reinterpret_cast<const float4*>(ea + (size_t)e * ED_F);
        #pragma unroll
        for (int i = 0; i < 4; i++) q[i] = eav[i];
        float a0 = 0.f, a1 = 0.f, a2 = 0.f, a3 = 0.f, a4 = 0.f;
        #pragma unroll
        for (int i = 0; i < 4; i++) {
            const float* v = &q[i].x;
            #pragma unroll
            for (int j = 0; j < 4; j++) {
                int d = i * 4 + j;
                float vv = v[j];
                float4 w = swae1[d];
                a0 += vv * w.x;
                a1 += vv * w.y;
                a2 += vv * w.z;
                a3 += vv * w.w;
                a4 += vv * swae2[d];
            }
        }
        int se, de;
        load_edge(eidx, e, g_is64, se, de);
        int pos = atomicAdd(&g_cursor[de], 1);
        __stcs(&g_rec[2 * (size_t)pos],     make_float4(a0, a1, a2, a3));
        __stcs(&g_rec[2 * (size_t)pos + 1], make_float4(a4, __int_as_float(se), 0.f, 0.f));
    } else {
        #pragma unroll
        for (int i = 0; i < 4; i++) q[i] = make_float4(0.f, 0.f, 0.f, 0.f);
    }
    #pragma unroll
    for (int o = 16; o; o >>= 1) {
        #pragma unroll
        for (int i = 0; i < 4; i++) {
            q[i].x += __shfl_xor_sync(FULL, q[i].x, o);
            q[i].y += __shfl_xor_sync(FULL, q[i].y, o);
            q[i].z += __shfl_xor_sync(FULL, q[i].z, o);
            q[i].w += __shfl_xor_sync(FULL, q[i].w, o);
        }
    }
    if ((threadIdx.x & 31) == 0) {
        #pragma unroll
        for (int i = 0; i < 4; i++) {
            atomicAdd(&s16[i * 4 + 0], q[i].x);
            atomicAdd(&s16[i * 4 + 1], q[i].y);
            atomicAdd(&s16[i * 4 + 2], q[i].z);
            atomicAdd(&s16[i * 4 + 3], q[i].w);
        }
    }
    __syncthreads();
    if (threadIdx.x < ED_F) atomicAdd(&g_emean[threadIdx.x], s16[threadIdx.x]);
}

// ---------------- self-loop fill ----------------
__global__ void selfloop_fill() {
    __shared__ float sl1s[HEADS];
    __shared__ float sl2s;
    int t = threadIdx.x;
    const float inv_e = 1.f / (float)EE;
    if (t < HEADS) {
        float s = 0.f;
        #pragma unroll
        for (int d = 0; d < ED_F; d++) s += g_emean[d] * inv_e * g_wae1[d * HEADS + t];
        sl1s[t] = s;
    } else if (t == HEADS) {
        float s = 0.f;
        #pragma unroll
        for (int d = 0; d < ED_F; d++) s += g_emean[d] * inv_e * g_wae2[d];
        sl2s = s;
    }
    __syncthreads();
    int n = blockIdx.x * blockDim.x + t;
    if (n >= NN) return;
    int j = g_rowstart[n];
    g_rec[2 * (size_t)j]     = make_float4(sl1s[0], sl1s[1], sl1s[2], sl1s[3]);
    g_rec[2 * (size_t)j + 1] = make_float4(sl2s, __int_as_float(n), 0.f, 0.f);
}

// ---------------- GEMM1 (FFMA2): h1(fp16) = x @ W1, fused coef1 ----------------
__global__ void gemm1(const float* __restrict__ A, const float* __restrict__ B,
                      const float* __restrict__ as1, const float* __restrict__ ad1) {
    __shared__ float As[64][IN_F + 4];
    __shared__ float Bst[32][IN_F + 2];
    int row0 = blockIdx.x * 64;
    int tx = threadIdx.x & 31;
    int ty = threadIdx.x >> 5;
    {
        const float4* A4 = reinterpret_cast<const float4*>(A);
        #pragma unroll
        for (int i = 0; i < 8; i++) {
            int idx = threadIdx.x + i * 256;
            int r = idx >> 5, c4 = idx & 31;
            int gr = row0 + r;
            float4 v = (gr < NN) ? A4[(size_t)gr * 32 + c4] : make_float4(0.f, 0.f, 0.f, 0.f);
            *reinterpret_cast<float4*>(&As[r][c4 * 4]) = v;
        }
    }
    for (int cb = 0; cb < HEADS; cb++) {
        __syncthreads();
        #pragma unroll
        for (int i = 0; i < 16; i++) {
            int idx = threadIdx.x + i * 256;
            int r = idx >> 5, c = idx & 31;
            Bst[c][r] = B[(size_t)r * F1 + cb * 32 + c];
        }
        __syncthreads();
        unsigned long long acc2[8];
        #pragma unroll
        for (int r = 0; r < 8; r++) acc2[r] = 0ull;
        #pragma unroll 4
        for (int k2 = 0; k2 < IN_F / 2; k2++) {
            unsigned long long bv = *reinterpret_cast<const unsigned long long*>(&Bst[tx][k2 * 2]);
            #pragma unroll
            for (int r = 0; r < 8; r++) {
                unsigned long long av =
                    *reinterpret_cast<const unsigned long long*>(&As[ty * 8 + r][k2 * 2]);
                acc2[r] = fma2(av, bv, acc2[r]);
            }
        }
        float asv = as1[cb * HID + tx];
        float adv = ad1[cb * HID + tx];
        #pragma unroll
        for (int r = 0; r < 8; r++) {
            float acc = pairsum(acc2[r]);
            int gr = row0 + ty * 8 + r;
            if (gr < NN) g_h1h[(size_t)gr * F1 + cb * 32 + tx] = __float2half_rn(acc);
            float sv = acc * asv;
            float dv = acc * adv;
            #pragma unroll
            for (int o = 16; o; o >>= 1) {
                sv += __shfl_xor_sync(FULL, sv, o);
                dv += __shfl_xor_sync(FULL, dv, o);
            }
            if (tx == 0 && gr < NN) {
                g_asrc1[gr * HEADS + cb] = sv;
                g_adst1[gr * HEADS + cb] = dv;
            }
        }
    }
}

// ---------------- aggregate layer 1 (8-edge unroll, fp16 gather) ----------------
__global__ void aggregate1(const float* __restrict__ b1) {
    int n = (blockIdx.x * blockDim.x + threadIdx.x) >> 5;
    if (n >= NN) return;
    int lane = threadIdx.x & 31;
    int beg = g_rowstart[n];
    int end = beg + g_count[n] + 1;
    int h4 = lane & 3;
    int hh = lane >> 3;
    float adst = g_adst1[n * HEADS + h4];
    float denp = 0.f;
    float4 acc = make_float4(0.f, 0.f, 0.f, 0.f);
    int j = beg;
    for (; j + 8 <= end; j += 8) {
        // lanes 0..7 hold edge records for edges j..j+7
        int sKl = 0;
        if (lane < 8)
            sKl = __float_as_int(
                reinterpret_cast<const float2*>(&g_rec[2 * (size_t)(j + lane) + 1])->y);
        // exp for all 32 (edge k = lane>>2, head h4 = lane&3)
        int k = lane >> 2;
        int skm = __shfl_sync(FULL, sKl, k);
        float aed = ((const float*)&g_rec[2 * (size_t)(j + k)])[h4];
        float lg = g_asrc1[skm * HEADS + h4] + adst + aed;
        lg = (lg > 0.f) ? lg : NEG_SLOPE * lg;
        float ex = __expf(lg);
        denp += ex;
        // 8 independent gathers
        #pragma unroll
        for (int kk = 0; kk < 8; kk++) {
            int s = __shfl_sync(FULL, sKl, kk);
            float e = __shfl_sync(FULL, ex, kk * 4 + hh);
            float4 v = gather_h4(&g_h1h[(size_t)s * F1 + lane * 4]);
            acc.x += e * v.x;
            acc.y += e * v.y;
            acc.z += e * v.z;
            acc.w += e * v.w;
        }
    }
    for (; j < end; j++) {
        float2 sb = *reinterpret_cast<const float2*>(&g_rec[2 * (size_t)j + 1]);
        int se = __float_as_int(sb.y);
        float ex = 0.f;
        if (lane < 4) {
            float aed = ((const float*)&g_rec[2 * (size_t)j])[lane];
            float lg = g_asrc1[se * HEADS + lane] + adst + aed;
            lg = (lg > 0.f) ? lg : NEG_SLOPE * lg;
            ex = __expf(lg);
            denp += ex;
        }
        float eb = __shfl_sync(FULL, ex, hh);
        float4 v = gather_h4(&g_h1h[(size_t)se * F1 + lane * 4]);
        acc.x += eb * v.x;
        acc.y += eb * v.y;
        acc.z += eb * v.z;
        acc.w += eb * v.w;
    }
    // reduce denp over lanes sharing h4 (offsets 4,8,16 sum across k-groups)
    denp += __shfl_xor_sync(FULL, denp, 4);
    denp += __shfl_xor_sync(FULL, denp, 8);
    denp += __shfl_xor_sync(FULL, denp, 16);
    float den = __shfl_sync(FULL, denp, hh);   // lane hh has h4 == hh
    float inv = 1.f / (den + 1e-16f);
    float4 bv = *reinterpret_cast<const float4*>(&b1[lane * 4]);
    float4 o;
    o.x = fmaxf(acc.x * inv + bv.x, 0.f);
    o.y = fmaxf(acc.y * inv + bv.y, 0.f);
    o.z = fmaxf(acc.z * inv + bv.z, 0.f);
    o.w = fmaxf(acc.w * inv + bv.w, 0.f);
    *reinterpret_cast<float4*>(&g_hr[(size_t)n * F1 + lane * 4]) = o;
}

// ---------------- GEMM2 (FFMA2): h2(fp16) = hr @ W2, fused coef2 ----------------
__global__ void gemm2(const float* __restrict__ B,
                      const float* __restrict__ as2, const float* __restrict__ ad2) {
    __shared__ float As[64][F1 + 4];
    __shared__ float Bst[32][F1 + 2];
    int row0 = blockIdx.x * 64;
    int tx = threadIdx.x & 31;
    int ty = threadIdx.x >> 5;
    {
        const float4* A4 = reinterpret_cast<const float4*>(g_hr);
        #pragma unroll
        for (int i = 0; i < 8; i++) {
            int idx = threadIdx.x + i * 256;
            int r = idx >> 5, c4 = idx & 31;
            int gr = row0 + r;
            float4 v = (gr < NN) ? A4[(size_t)gr * 32 + c4] : make_float4(0.f, 0.f, 0.f, 0.f);
            *reinterpret_cast<float4*>(&As[r][c4 * 4]) = v;
        }
    }
    #pragma unroll
    for (int i = 0; i < 16; i++) {
        int idx = threadIdx.x + i * 256;
        int r = idx >> 5, c = idx & 31;
        Bst[c][r] = B[(size_t)r * OUTF + c];
    }
    __syncthreads();
    unsigned long long acc2[8];
    #pragma unroll
    for (int r = 0; r < 8; r++) acc2[r] = 0ull;
    #pragma unroll 4
    for (int k2 = 0; k2 < F1 / 2; k2++) {
        unsigned long long bv = *reinterpret_cast<const unsigned long long*>(&Bst[tx][k2 * 2]);
        #pragma unroll
        for (int r = 0; r < 8; r++) {
            unsigned long long av =
                *reinterpret_cast<const unsigned long long*>(&As[ty * 8 + r][k2 * 2]);
            acc2[r] = fma2(av, bv, acc2[r]);
        }
    }
    float asv = as2[tx];
    float adv = ad2[tx];
    #pragma unroll
    for (int r = 0; r < 8; r++) {
        float acc = pairsum(acc2[r]);
        int gr = row0 + ty * 8 + r;
        if (gr < NN) g_h2h[(size_t)gr * OUTF + tx] = __float2half_rn(acc);
        float sv = acc * asv;
        float dv = acc * adv;
        #pragma unroll
        for (int o = 16; o; o >>= 1) {
            sv += __shfl_xor_sync(FULL, sv, o);
            dv += __shfl_xor_sync(FULL, dv, o);
        }
        if (tx == 0 && gr < NN) {
            g_asrc2[gr] = sv;
            g_adst2[gr] = dv;
        }
    }
}

// ---------------- aggregate layer 2 (8-edge unroll, fp16 gather) ----------------
__global__ void aggregate2(float* __restrict__ out, const float* __restrict__ b2) {
    int n = (blockIdx.x * blockDim.x + threadIdx.x) >> 5;
    if (n >= NN) return;
    int lane = threadIdx.x & 31;
    int beg = g_rowstart[n];
    int end = beg + g_count[n] + 1;
    float adst = g_adst2[n];
    float denp = 0.f, acc = 0.f;
    int j = beg;
    for (; j + 8 <= end; j += 8) {
        int sKl = 0;
        float ex = 0.f;
        if (lane < 8) {
            float2 sbv = *reinterpret_cast<const float2*>(&g_rec[2 * (size_t)(j + lane) + 1]);
            sKl = __float_as_int(sbv.y);
            float lg = g_asrc2[sKl] + adst + sbv.x;
            lg = (lg > 0.f) ? lg : NEG_SLOPE * lg;
            ex = __expf(lg);
            denp += ex;
        }
        #pragma unroll
        for (int kk = 0; kk < 8; kk++) {
            int s = __shfl_sync(FULL, sKl, kk);
            float e = __shfl_sync(FULL, ex, kk);
            acc += e * __half2float(g_h2h[(size_t)s * OUTF + lane]);
        }
    }
    for (; j < end; j++) {
        float2 sb = *reinterpret_cast<const float2*>(&g_rec[2 * (size_t)j + 1]);
        int se = __float_as_int(sb.y);
        float ex = 0.f;
        if (lane == 0) {
            float lg = g_asrc2[se] + adst + sb.x;
            lg = (lg > 0.f) ? lg : NEG_SLOPE * lg;
            ex = __expf(lg);
            denp += ex;
        }
        float eb = __shfl_sync(FULL, ex, 0);
        acc += eb * __half2float(g_h2h[(size_t)se * OUTF + lane]);
    }
    denp += __shfl_xor_sync(FULL, denp, 1);
    denp += __shfl_xor_sync(FULL, denp, 2);
    denp += __shfl_xor_sync(FULL, denp, 4);
    denp += __shfl_xor_sync(FULL, denp, 8);
    denp += __shfl_xor_sync(FULL, denp, 16);
    out[(size_t)n * OUTF + lane] = acc / (denp + 1e-16f) + b2[lane];
}

// ---------------- launch ----------------
extern "C" void kernel_launch(void* const* d_in, const int* in_sizes, int n_in,
                              void* d_out, int out_size) {
    int used[64];
    for (int i = 0; i < n_in && i < 64; i++) used[i] = 0;
    auto take = [&](int want) -> const void* {
        for (int i = 0; i < n_in && i < 64; i++)
            if (!used[i] && in_sizes[i] == want) { used[i] = 1; return d_in[i]; }
        return nullptr;
    };
    const float* x   = (const float*)take(NN * IN_F);
    const void*  eix = take(2 * EE);
    const float* ea  = (const float*)take(EE * ED_F);
    const float* W1  = (const float*)take(IN_F * F1);
    const float* We1 = (const float*)take(ED_F * F1);
    const float* W2  = (const float*)take(F1 * OUTF);
    const float* We2 = (const float*)take(ED_F * OUTF);
    const float* g128[4] = {nullptr, nullptr, nullptr, nullptr};
    const float* g32[4]  = {nullptr, nullptr, nullptr, nullptr};
    int n128 = 0, n32 = 0;
    for (int i = 0; i < n_in && i < 64; i++) {
        if (used[i]) continue;
        if (in_sizes[i] == 128 && n128 < 4) g128[n128++] = (const float*)d_in[i];
        else if (in_sizes[i] == 32 && n32 < 4) g32[n32++] = (const float*)d_in[i];
    }
    const float* as1 = g128[0], *ad1 = g128[1], *ae1 = g128[2], *b1 = g128[3];
    const float* as2 = g32[0],  *ad2 = g32[1],  *ae2 = g32[2],  *b2 = g32[3];
    if (!x || !eix || !ea || !W1 || !We1 || !W2 || !We2 || n128 < 4 || n32 < 4) {
        x   = (const float*)d_in[0];  eix = d_in[1];               ea  = (const float*)d_in[2];
        W1  = (const float*)d_in[3];  We1 = (const float*)d_in[4];
        as1 = (const float*)d_in[5];  ad1 = (const float*)d_in[6]; ae1 = (const float*)d_in[7];
        b1  = (const float*)d_in[8];  W2  = (const float*)d_in[9]; We2 = (const float*)d_in[10];
        as2 = (const float*)d_in[11]; ad2 = (const float*)d_in[12]; ae2 = (const float*)d_in[13];
        b2  = (const float*)d_in[14];
    }
    float* out = (float*)d_out;

    const int TB = 256;

    static cudaStream_t s2 = nullptr;
    static cudaEvent_t e1 = nullptr, e2 = nullptr;
    if (!s2) {
        cudaStreamCreateWithFlags(&s2, cudaStreamNonBlocking);
        cudaEventCreateWithFlags(&e1, cudaEventDisableTiming);
        cudaEventCreateWithFlags(&e2, cudaEventDisableTiming);
    }

    // fork gemm1 (independent of CSR chain)
    cudaEventRecord(e1, 0);
    cudaStreamWaitEvent(s2, e1, 0);
    gemm1<<<(NN + 63) / 64, TB, 0, s2>>>(x, W1, as1, ad1);
    cudaEventRecord(e2, s2);

    setup<<<(NN + TB - 1) / TB, TB>>>(eix, We1, ae1, We2, ae2);
    count_edges<<<(EE + TB * 4 - 1) / (TB * 4), TB>>>(eix);
    assign_rows<<<(NN + TB - 1) / TB, TB>>>();
    edge_dots_scatter<<<(EE + TB - 1) / TB, TB>>>(eix, ea);
    selfloop_fill<<<(NN + TB - 1) / TB, TB>>>();

    cudaStreamWaitEvent(0, e2, 0);

    aggregate1<<<(int)(((size_t)NN * 32 + TB - 1) / TB), TB>>>(b1);
    gemm2<<<(NN + 63) / 64, TB>>>(W2, as2, ad2);
    aggregate2<<<(int)(((size_t)NN * 32 + TB - 1) / TB), TB>>>(out, b2);
}